// round 2
// baseline (speedup 1.0000x reference)
#include <cuda_runtime.h>
#include <cstdint>

#define BB 64
#define TT 256
#define ET 1024
#define UDIM 512
#define VV 46
#define N4 2048
#define KDIM 1024
#define KSPLIT 4
#define KCH 256

// ---------------- device-global state / scratch (allocation-free) ----------------
__device__ __align__(16) float g_M1[KDIM * N4];   // rows 0..511: W1[0:512]+U1 ; rows 512..1023: W1[513:1025]
__device__ __align__(16) float g_M2[KDIM * N4];   // rows 0..511: W2 ; rows 512..1023: U2
__device__ __align__(16) float g_r1[N4];          // W1 row 512 (the y_t rank-1 term)
__device__ __align__(16) float g_WdT[VV * KDIM];  // Wd transposed [v][k]
__device__ __align__(16) float g_h1[BB * UDIM];
__device__ __align__(16) float g_c1[BB * UDIM];
__device__ __align__(16) float g_h2[BB * UDIM];
__device__ __align__(16) float g_c2[BB * UDIM];
__device__ __align__(16) float g_ctx[BB * UDIM];
__device__ __align__(16) float g_z1p[KSPLIT * BB * N4];  // split-K partials for LSTM1 pre-activations
__device__ __align__(16) float g_z2p[KSPLIT * BB * N4];  // split-K partials for LSTM2 pre-activations

__device__ __forceinline__ float sigf(float x) { return 1.f / (1.f + __expf(-x)); }

// ---------------- prologue: combine weights, transpose Wd, zero state ----------------
__global__ void prologue_kernel(const float* __restrict__ W1, const float* __restrict__ U1,
                                const float* __restrict__ W2, const float* __restrict__ U2,
                                const float* __restrict__ Wd) {
    int stride = gridDim.x * blockDim.x;
    int t0 = blockIdx.x * blockDim.x + threadIdx.x;
    for (int idx = t0; idx < KDIM * N4; idx += stride) {
        int k = idx >> 11;          // /2048
        int j = idx & (N4 - 1);
        g_M1[idx] = (k < UDIM) ? (W1[k * N4 + j] + U1[k * N4 + j]) : W1[(k + 1) * N4 + j];
        g_M2[idx] = (k < UDIM) ? W2[k * N4 + j] : U2[(k - UDIM) * N4 + j];
    }
    for (int j = t0; j < N4; j += stride) g_r1[j] = W1[UDIM * N4 + j];
    for (int idx = t0; idx < VV * KDIM; idx += stride) {
        int v = idx / KDIM, k = idx % KDIM;
        g_WdT[idx] = Wd[k * VV + v];
    }
    for (int i = t0; i < BB * UDIM; i += stride) {
        g_h1[i] = 0.f; g_c1[i] = 0.f; g_h2[i] = 0.f; g_c2[i] = 0.f; g_ctx[i] = 0.f;
    }
}

// ---------------- shared split-K GEMM tile body: 64x64 tile, K-chunk of 256 ----------------
// A(b,k) = k<512 ? A0[b*512+k] : A1[b*512+k-512]   (k-chunks are 256-aligned, so one source per block)
__device__ __forceinline__ void gemm_body(int id, const float* __restrict__ A0,
                                          const float* __restrict__ A1,
                                          const float* __restrict__ Mw,
                                          float* __restrict__ zp) {
    int jt = id & 31;
    int kc = id >> 5;
    int jbase = jt * 64;
    int kcbase = kc * KCH;
    const float* A = (kcbase < UDIM) ? A0 : A1;
    int koff = kcbase & (UDIM - 1);

    __shared__ __align__(16) float As[64][16];
    __shared__ __align__(16) float Bs[16][64];

    int tid = threadIdx.x;
    int tx = tid & 15, ty = tid >> 4;
    int alb = tid >> 2, alk = (tid & 3) * 4;
    int bkk = tid >> 4, bj = (tid & 15) * 4;

    float acc[4][4];
#pragma unroll
    for (int i = 0; i < 4; ++i)
#pragma unroll
        for (int j = 0; j < 4; ++j) acc[i][j] = 0.f;

    for (int s = 0; s < KCH / 16; ++s) {
        float4 av = *(const float4*)(A + alb * UDIM + koff + s * 16 + alk);
        *(float4*)&As[alb][alk] = av;
        float4 bv = *(const float4*)(Mw + (size_t)(kcbase + s * 16 + bkk) * N4 + jbase + bj);
        *(float4*)&Bs[bkk][bj] = bv;
        __syncthreads();
#pragma unroll
        for (int kk = 0; kk < 16; ++kk) {
            float a0 = As[ty * 4 + 0][kk];
            float a1 = As[ty * 4 + 1][kk];
            float a2 = As[ty * 4 + 2][kk];
            float a3 = As[ty * 4 + 3][kk];
            float4 b4 = *(const float4*)&Bs[kk][tx * 4];
            acc[0][0] += a0 * b4.x; acc[0][1] += a0 * b4.y; acc[0][2] += a0 * b4.z; acc[0][3] += a0 * b4.w;
            acc[1][0] += a1 * b4.x; acc[1][1] += a1 * b4.y; acc[1][2] += a1 * b4.z; acc[1][3] += a1 * b4.w;
            acc[2][0] += a2 * b4.x; acc[2][1] += a2 * b4.y; acc[2][2] += a2 * b4.z; acc[2][3] += a2 * b4.w;
            acc[3][0] += a3 * b4.x; acc[3][1] += a3 * b4.y; acc[3][2] += a3 * b4.z; acc[3][3] += a3 * b4.w;
        }
        __syncthreads();
    }
    float* zb = zp + (size_t)kc * BB * N4;
#pragma unroll
    for (int i = 0; i < 4; ++i) {
        float4 o;
        o.x = acc[i][0]; o.y = acc[i][1]; o.z = acc[i][2]; o.w = acc[i][3];
        *(float4*)(zb + (ty * 4 + i) * N4 + jbase + tx * 4) = o;
    }
}

// ---------------- LSTM2 gate finish + logits + output softmax for step tprev ----------------
__device__ __forceinline__ void dec_body(int b, int tprev, const float* __restrict__ b2,
                                         const float* __restrict__ bd, float* __restrict__ out) {
    __shared__ __align__(16) float xcat[2 * UDIM];
    __shared__ float lg[VV];
    int tid = threadIdx.x;
#pragma unroll
    for (int r = 0; r < 2; ++r) {
        int u = tid + r * 256;
        float z[4];
#pragma unroll
        for (int g = 0; g < 4; ++g) {
            int idx = g * UDIM + u;
            float v = b2[idx];
#pragma unroll
            for (int kc = 0; kc < KSPLIT; ++kc) v += g_z2p[(kc * BB + b) * N4 + idx];
            z[g] = v;
        }
        float co = g_c2[b * UDIM + u];
        float cn = sigf(z[1]) * co + sigf(z[0]) * tanhf(z[2]);
        float hn = sigf(z[3]) * tanhf(cn);
        g_c2[b * UDIM + u] = cn;
        g_h2[b * UDIM + u] = hn;
        xcat[u] = hn;
        xcat[UDIM + u] = g_ctx[b * UDIM + u];
    }
    __syncthreads();
    int lane = tid & 31, w = tid >> 5;
    for (int v = w; v < VV; v += 8) {
        float p = 0.f;
        const float* wr = g_WdT + v * KDIM;
        for (int k = lane; k < KDIM; k += 32) p += xcat[k] * wr[k];
#pragma unroll
        for (int off = 16; off; off >>= 1) p += __shfl_xor_sync(0xffffffffu, p, off);
        if (lane == 0) lg[v] = p + bd[v];
    }
    __syncthreads();
    if (tid == 0) {
        float mx = lg[0];
        for (int v = 1; v < VV; ++v) mx = fmaxf(mx, lg[v]);
        float s = 0.f;
        for (int v = 0; v < VV; ++v) { float e = __expf(lg[v] - mx); lg[v] = e; s += e; }
        float inv = 1.f / s;
        for (int v = 0; v < VV; ++v) lg[v] *= inv;
    }
    __syncthreads();
    if (tid < VV) out[((size_t)b * TT + tprev) * VV + tid] = lg[tid];
}

// ---------------- KA: z1 GEMM (blocks 0..127) + prev-step LSTM2 gates/logits (128..191) ----------------
__global__ void __launch_bounds__(256) ka_kernel(const float* __restrict__ b2,
                                                 const float* __restrict__ bd,
                                                 float* __restrict__ out, int t) {
    if (blockIdx.x < 128) {
        gemm_body(blockIdx.x, g_h1, g_ctx, g_M1, g_z1p);
    } else if (t > 0) {
        dec_body(blockIdx.x - 128, t - 1, b2, bd, out);
    }
}

// ---------------- KC: z2 GEMM ----------------
__global__ void __launch_bounds__(256) kc_kernel() {
    gemm_body(blockIdx.x, g_ctx, g_h2, g_M2, g_z2p);
}

// ---------------- epilogue: last step's gates + logits ----------------
__global__ void __launch_bounds__(256) ep_kernel(const float* __restrict__ b2,
                                                 const float* __restrict__ bd,
                                                 float* __restrict__ out) {
    dec_body(blockIdx.x, TT - 1, b2, bd, out);
}

// ---------------- KB: LSTM1 gate finish + single-pass online-softmax attention ----------------
// One block per batch row. h tile (32 frames x 512) held in registers; h read exactly once.
__global__ void __launch_bounds__(256) attn_kernel(const float* __restrict__ h,
                                                   const float* __restrict__ yv,
                                                   const float* __restrict__ b1, int t) {
    int b = blockIdx.x;
    int tid = threadIdx.x;
    __shared__ __align__(16) float h1s[UDIM];
    __shared__ float scs[32];
    __shared__ __align__(16) float reds[8][UDIM];
    __shared__ float swarp[8];

    float yb = yv[b * TT + t];
#pragma unroll
    for (int r = 0; r < 2; ++r) {
        int u = tid + r * 256;
        float z[4];
#pragma unroll
        for (int g = 0; g < 4; ++g) {
            int idx = g * UDIM + u;
            float vvv = b1[idx] + yb * g_r1[idx];
#pragma unroll
            for (int kc = 0; kc < KSPLIT; ++kc) vvv += g_z1p[(kc * BB + b) * N4 + idx];
            z[g] = vvv;
        }
        float co = g_c1[b * UDIM + u];
        float cn = sigf(z[1]) * co + sigf(z[0]) * tanhf(z[2]);
        float hn = sigf(z[3]) * tanhf(cn);
        g_c1[b * UDIM + u] = cn;
        g_h1[b * UDIM + u] = hn;
        h1s[u] = hn;
    }
    __syncthreads();

    int lane = tid & 31, w = tid >> 5;
    float4 h1r[4];
#pragma unroll
    for (int i = 0; i < 4; ++i) h1r[i] = *(const float4*)&h1s[lane * 4 + i * 128];

    float4 acc[4];
#pragma unroll
    for (int i = 0; i < 4; ++i) { acc[i].x = 0.f; acc[i].y = 0.f; acc[i].z = 0.f; acc[i].w = 0.f; }
    float m = -1e30f, sw = 0.f;
    const float* hb = h + (size_t)b * ET * UDIM;

    for (int tile = 0; tile < ET / 32; ++tile) {
        const float* hf = hb + (size_t)(tile * 32 + w * 4) * UDIM;
        float4 v0[4], v1[4], v2[4], v3[4];
#pragma unroll
        for (int i = 0; i < 4; ++i) {
            v0[i] = *(const float4*)&hf[lane * 4 + i * 128];
            v1[i] = *(const float4*)&hf[UDIM + lane * 4 + i * 128];
            v2[i] = *(const float4*)&hf[2 * UDIM + lane * 4 + i * 128];
            v3[i] = *(const float4*)&hf[3 * UDIM + lane * 4 + i * 128];
        }
        float s0 = 0.f, s1 = 0.f, s2 = 0.f, s3 = 0.f;
#pragma unroll
        for (int i = 0; i < 4; ++i) {
            s0 += v0[i].x * h1r[i].x + v0[i].y * h1r[i].y + v0[i].z * h1r[i].z + v0[i].w * h1r[i].w;
            s1 += v1[i].x * h1r[i].x + v1[i].y * h1r[i].y + v1[i].z * h1r[i].z + v1[i].w * h1r[i].w;
            s2 += v2[i].x * h1r[i].x + v2[i].y * h1r[i].y + v2[i].z * h1r[i].z + v2[i].w * h1r[i].w;
            s3 += v3[i].x * h1r[i].x + v3[i].y * h1r[i].y + v3[i].z * h1r[i].z + v3[i].w * h1r[i].w;
        }
#pragma unroll
        for (int off = 16; off; off >>= 1) {
            s0 += __shfl_xor_sync(0xffffffffu, s0, off);
            s1 += __shfl_xor_sync(0xffffffffu, s1, off);
            s2 += __shfl_xor_sync(0xffffffffu, s2, off);
            s3 += __shfl_xor_sync(0xffffffffu, s3, off);
        }
        if (lane == 0) {
            scs[w * 4 + 0] = s0; scs[w * 4 + 1] = s1;
            scs[w * 4 + 2] = s2; scs[w * 4 + 3] = s3;
        }
        __syncthreads();
        float tv = scs[lane];
#pragma unroll
        for (int off = 16; off; off >>= 1) tv = fmaxf(tv, __shfl_xor_sync(0xffffffffu, tv, off));
        float mn = fmaxf(m, tv);
        float scale = __expf(m - mn);
        m = mn;
        float p0 = __expf(s0 - mn), p1 = __expf(s1 - mn);
        float p2 = __expf(s2 - mn), p3 = __expf(s3 - mn);
        sw = sw * scale + (p0 + p1 + p2 + p3);
#pragma unroll
        for (int i = 0; i < 4; ++i) {
            acc[i].x = acc[i].x * scale + p0 * v0[i].x + p1 * v1[i].x + p2 * v2[i].x + p3 * v3[i].x;
            acc[i].y = acc[i].y * scale + p0 * v0[i].y + p1 * v1[i].y + p2 * v2[i].y + p3 * v3[i].y;
            acc[i].z = acc[i].z * scale + p0 * v0[i].z + p1 * v1[i].z + p2 * v2[i].z + p3 * v3[i].z;
            acc[i].w = acc[i].w * scale + p0 * v0[i].w + p1 * v1[i].w + p2 * v2[i].w + p3 * v3[i].w;
        }
        __syncthreads();
    }
#pragma unroll
    for (int i = 0; i < 4; ++i) *(float4*)&reds[w][lane * 4 + i * 128] = acc[i];
    if (lane == 0) swarp[w] = sw;
    __syncthreads();
    float stot = 0.f;
#pragma unroll
    for (int ww = 0; ww < 8; ++ww) stot += swarp[ww];
    float inv = 1.f / stot;
#pragma unroll
    for (int r = 0; r < 2; ++r) {
        int d = tid + r * 256;
        float a = 0.f;
#pragma unroll
        for (int ww = 0; ww < 8; ++ww) a += reds[ww][d];
        g_ctx[b * UDIM + d] = a * inv;
    }
}

// ---------------- launcher (graph-capturable: kernel launches only) ----------------
extern "C" void kernel_launch(void* const* d_in, const int* in_sizes, int n_in,
                              void* d_out, int out_size) {
    (void)in_sizes; (void)n_in; (void)out_size;
    const float* h  = (const float*)d_in[0];
    const float* y  = (const float*)d_in[1];
    const float* W1 = (const float*)d_in[2];
    const float* U1 = (const float*)d_in[3];
    const float* b1 = (const float*)d_in[4];
    const float* W2 = (const float*)d_in[5];
    const float* U2 = (const float*)d_in[6];
    const float* b2 = (const float*)d_in[7];
    const float* Wd = (const float*)d_in[8];
    const float* bd = (const float*)d_in[9];
    float* out = (float*)d_out;

    prologue_kernel<<<1024, 256>>>(W1, U1, W2, U2, Wd);
    for (int t = 0; t < TT; ++t) {
        ka_kernel<<<192, 256>>>(b2, bd, out, t);
        attn_kernel<<<64, 256>>>(h, y, b1, t);
        kc_kernel<<<128, 256>>>();
    }
    ep_kernel<<<64, 256>>>(b2, bd, out);
}

// round 3
// speedup vs baseline: 1.4037x; 1.4037x over previous
#include <cuda_runtime.h>
#include <cuda_fp16.h>
#include <cstdint>

#define BB 64
#define TT 256
#define ET 1024
#define UDIM 512
#define VV 46
#define N4 2048
#define KDIM 1024
#define KSPLIT 16
#define KCH 64
#define TN 256

// ---------------- device-global state / scratch (allocation-free) ----------------
__device__ __align__(16) float g_M1[KDIM * N4];   // rows 0..511: W1[0:512]+U1 ; rows 512..1023: W1[513:1025]
__device__ __align__(16) float g_M2[KDIM * N4];   // rows 0..511: W2 ; rows 512..1023: U2
__device__ __align__(16) float g_r1[N4];          // W1 row 512 (y_t rank-1 term)
__device__ __align__(16) float g_WdT[VV * KDIM];  // Wd transposed [v][k]
__device__ __align__(16) __half g_hh[(size_t)BB * ET * UDIM];  // fp16 copy of encoder h
__device__ __align__(16) float g_h1[BB * UDIM];
__device__ __align__(16) float g_c1[BB * UDIM];
__device__ __align__(16) float g_h2[BB * UDIM];
__device__ __align__(16) float g_c2[BB * UDIM];
__device__ __align__(16) float g_ctx[BB * UDIM];
__device__ __align__(16) float g_z1p[KSPLIT * BB * N4];
__device__ __align__(16) float g_z2p[KSPLIT * BB * N4];

__device__ __forceinline__ float sigf(float x) { return 1.f / (1.f + __expf(-x)); }

__device__ __forceinline__ void cpa16(void* smem, const void* g) {
    unsigned s = (unsigned)__cvta_generic_to_shared(smem);
    asm volatile("cp.async.cg.shared.global [%0], [%1], 16;" :: "r"(s), "l"(g));
}
__device__ __forceinline__ void cpcommit() { asm volatile("cp.async.commit_group;"); }
template <int N> __device__ __forceinline__ void cpwait() {
    asm volatile("cp.async.wait_group %0;" :: "n"(N));
}

// ---------------- prologue: combine weights, transpose Wd, fp16 h, zero state ----------------
__global__ void prologue_kernel(const float* __restrict__ W1, const float* __restrict__ U1,
                                const float* __restrict__ W2, const float* __restrict__ U2,
                                const float* __restrict__ Wd, const float* __restrict__ h) {
    int stride = gridDim.x * blockDim.x;
    int t0 = blockIdx.x * blockDim.x + threadIdx.x;
    for (int idx = t0; idx < KDIM * N4; idx += stride) {
        int k = idx >> 11;
        int j = idx & (N4 - 1);
        g_M1[idx] = (k < UDIM) ? (W1[k * N4 + j] + U1[k * N4 + j]) : W1[(k + 1) * N4 + j];
        g_M2[idx] = (k < UDIM) ? W2[k * N4 + j] : U2[(k - UDIM) * N4 + j];
    }
    for (int j = t0; j < N4; j += stride) g_r1[j] = W1[UDIM * N4 + j];
    for (int idx = t0; idx < VV * KDIM; idx += stride) {
        int v = idx / KDIM, k = idx % KDIM;
        g_WdT[idx] = Wd[k * VV + v];
    }
    for (size_t idx = t0; idx < (size_t)BB * ET * UDIM; idx += stride)
        g_hh[idx] = __float2half_rn(h[idx]);
    for (int i = t0; i < BB * UDIM; i += stride) {
        g_h1[i] = 0.f; g_c1[i] = 0.f; g_h2[i] = 0.f; g_c2[i] = 0.f; g_ctx[i] = 0.f;
    }
}

// ---------------- split-K GEMM: 64x256 tile, 8x8 register blocking, cp.async pipeline ----------------
// A(b,k) = k<512 ? A0[b*512+k] : A1[b*512+k-512]
__device__ __forceinline__ void gemm_body(int id, const float* __restrict__ A0,
                                          const float* __restrict__ A1,
                                          const float* __restrict__ Mw,
                                          float* __restrict__ zp) {
    int jt = id & 7;           // 8 N-tiles of 256
    int kc = id >> 3;          // 16 K-chunks of 64
    int jbase = jt * TN;
    int kcbase = kc * KCH;
    const float* A = (kcbase < UDIM) ? A0 : A1;
    int koff = kcbase & (UDIM - 1);

    __shared__ __align__(16) float As[2][64][16];
    __shared__ __align__(16) float Bs[2][16][TN];

    int tid = threadIdx.x;
    int ar = tid >> 2;             // A load row 0..63
    int ak = (tid & 3) * 4;        // A load k-offset within stage
    int rbase = (tid >> 5) * 8;    // compute rows (warp -> 8 rows)
    int cbase = (tid & 31) * 8;    // compute cols (lane -> 8 cols)

    float acc[8][8];
#pragma unroll
    for (int i = 0; i < 8; ++i)
#pragma unroll
        for (int j = 0; j < 8; ++j) acc[i][j] = 0.f;

    // stage 0 issue
    {
        cpa16(&As[0][ar][ak], A + ar * UDIM + koff + ak);
#pragma unroll
        for (int q = 0; q < 4; ++q) {
            int f = tid * 4 + q;
            int kk = f >> 6;
            int c4 = (f & 63) * 4;
            cpa16(&Bs[0][kk][c4], Mw + (size_t)(kcbase + kk) * N4 + jbase + c4);
        }
        cpcommit();
    }

#pragma unroll 2
    for (int s = 0; s < 4; ++s) {
        if (s < 3) {
            int nb = (s + 1) & 1;
            cpa16(&As[nb][ar][ak], A + ar * UDIM + koff + (s + 1) * 16 + ak);
#pragma unroll
            for (int q = 0; q < 4; ++q) {
                int f = tid * 4 + q;
                int kk = f >> 6;
                int c4 = (f & 63) * 4;
                cpa16(&Bs[nb][kk][c4], Mw + (size_t)(kcbase + (s + 1) * 16 + kk) * N4 + jbase + c4);
            }
            cpcommit();
            cpwait<1>();
        } else {
            cpwait<0>();
        }
        __syncthreads();
        int bf = s & 1;
#pragma unroll
        for (int kk = 0; kk < 16; ++kk) {
            float a[8];
#pragma unroll
            for (int j = 0; j < 8; ++j) a[j] = As[bf][rbase + j][kk];
            float4 b0 = *(const float4*)&Bs[bf][kk][cbase];
            float4 b1v = *(const float4*)&Bs[bf][kk][cbase + 4];
            float bb[8] = {b0.x, b0.y, b0.z, b0.w, b1v.x, b1v.y, b1v.z, b1v.w};
#pragma unroll
            for (int i = 0; i < 8; ++i)
#pragma unroll
                for (int j = 0; j < 8; ++j) acc[i][j] += a[i] * bb[j];
        }
        __syncthreads();
    }

    float* zb = zp + (size_t)kc * BB * N4;
#pragma unroll
    for (int i = 0; i < 8; ++i) {
        float4 o0, o1;
        o0.x = acc[i][0]; o0.y = acc[i][1]; o0.z = acc[i][2]; o0.w = acc[i][3];
        o1.x = acc[i][4]; o1.y = acc[i][5]; o1.z = acc[i][6]; o1.w = acc[i][7];
        *(float4*)(zb + (size_t)(rbase + i) * N4 + jbase + cbase) = o0;
        *(float4*)(zb + (size_t)(rbase + i) * N4 + jbase + cbase + 4) = o1;
    }
}

// ---------------- LSTM2 gate finish + logits + output softmax for step tprev ----------------
__device__ __forceinline__ void dec_body(int b, int tprev, const float* __restrict__ b2,
                                         const float* __restrict__ bd, float* __restrict__ out) {
    __shared__ __align__(16) float xcat[2 * UDIM];
    __shared__ float lg[VV];
    int tid = threadIdx.x;
#pragma unroll
    for (int r = 0; r < 2; ++r) {
        int u = tid + r * 256;
        float z[4];
#pragma unroll
        for (int g = 0; g < 4; ++g) {
            int idx = g * UDIM + u;
            float v = b2[idx];
#pragma unroll
            for (int kc = 0; kc < KSPLIT; ++kc) v += g_z2p[(size_t)(kc * BB + b) * N4 + idx];
            z[g] = v;
        }
        float co = g_c2[b * UDIM + u];
        float cn = sigf(z[1]) * co + sigf(z[0]) * tanhf(z[2]);
        float hn = sigf(z[3]) * tanhf(cn);
        g_c2[b * UDIM + u] = cn;
        g_h2[b * UDIM + u] = hn;
        xcat[u] = hn;
        xcat[UDIM + u] = g_ctx[b * UDIM + u];
    }
    __syncthreads();
    int lane = tid & 31, w = tid >> 5;
    for (int v = w; v < VV; v += 8) {
        float p = 0.f;
        const float* wr = g_WdT + v * KDIM;
        for (int k = lane; k < KDIM; k += 32) p += xcat[k] * wr[k];
#pragma unroll
        for (int off = 16; off; off >>= 1) p += __shfl_xor_sync(0xffffffffu, p, off);
        if (lane == 0) lg[v] = p + bd[v];
    }
    __syncthreads();
    if (tid == 0) {
        float mx = lg[0];
        for (int v = 1; v < VV; ++v) mx = fmaxf(mx, lg[v]);
        float s = 0.f;
        for (int v = 0; v < VV; ++v) { float e = __expf(lg[v] - mx); lg[v] = e; s += e; }
        float inv = 1.f / s;
        for (int v = 0; v < VV; ++v) lg[v] *= inv;
    }
    __syncthreads();
    if (tid < VV) out[((size_t)b * TT + tprev) * VV + tid] = lg[tid];
}

// ---------------- KA: z1 GEMM (blocks 0..127) + prev-step LSTM2/logits (128..191) ----------------
__global__ void __launch_bounds__(256) ka_kernel(const float* __restrict__ b2,
                                                 const float* __restrict__ bd,
                                                 float* __restrict__ out, int t) {
    if (blockIdx.x < 128) {
        gemm_body(blockIdx.x, g_h1, g_ctx, g_M1, g_z1p);
    } else if (t > 0) {
        dec_body(blockIdx.x - 128, t - 1, b2, bd, out);
    }
}

__global__ void __launch_bounds__(256) kc_kernel() {
    gemm_body(blockIdx.x, g_ctx, g_h2, g_M2, g_z2p);
}

__global__ void __launch_bounds__(256) ep_kernel(const float* __restrict__ b2,
                                                 const float* __restrict__ bd,
                                                 float* __restrict__ out) {
    dec_body(blockIdx.x, TT - 1, b2, bd, out);
}

// ---------------- KB: LSTM1 gate finish + per-warp online-softmax attention over fp16 h ----------------
__global__ void __launch_bounds__(256) attn_kernel(const float* __restrict__ yv,
                                                   const float* __restrict__ b1, int t) {
    int b = blockIdx.x;
    int tid = threadIdx.x;
    int lane = tid & 31, w = tid >> 5;
    __shared__ __align__(16) float h1s[UDIM];
    __shared__ __align__(16) float reds[8][UDIM];
    __shared__ float mwarp[8], swarp[8];

    float yb = yv[b * TT + t];
#pragma unroll
    for (int r = 0; r < 2; ++r) {
        int u = tid + r * 256;
        float z[4];
#pragma unroll
        for (int g = 0; g < 4; ++g) {
            int idx = g * UDIM + u;
            float vvv = b1[idx] + yb * g_r1[idx];
#pragma unroll
            for (int kc = 0; kc < KSPLIT; ++kc) vvv += g_z1p[(size_t)(kc * BB + b) * N4 + idx];
            z[g] = vvv;
        }
        float co = g_c1[b * UDIM + u];
        float cn = sigf(z[1]) * co + sigf(z[0]) * tanhf(z[2]);
        float hn = sigf(z[3]) * tanhf(cn);
        g_c1[b * UDIM + u] = cn;
        g_h1[b * UDIM + u] = hn;
        h1s[u] = hn;
    }
    __syncthreads();

    float hr[16];
#pragma unroll
    for (int i = 0; i < 4; ++i) *(float4*)&hr[i * 4] = *(const float4*)&h1s[lane * 16 + i * 4];

    float acc[16];
#pragma unroll
    for (int j = 0; j < 16; ++j) acc[j] = 0.f;
    float m = -1e30f, sw = 0.f;
    const __half* hb = g_hh + (size_t)b * ET * UDIM;

    for (int tile = 0; tile < ET / 32; ++tile) {
        int f0 = tile * 32 + w * 4;
        float v[4][16];
        float sc[4];
#pragma unroll
        for (int fi = 0; fi < 4; ++fi) {
            const __half* hf = hb + (size_t)(f0 + fi) * UDIM + lane * 16;
            uint4 p0 = *(const uint4*)hf;
            uint4 p1 = *(const uint4*)(hf + 8);
            const unsigned pk[8] = {p0.x, p0.y, p0.z, p0.w, p1.x, p1.y, p1.z, p1.w};
#pragma unroll
            for (int q = 0; q < 8; ++q) {
                float2 f2 = __half22float2(*(const __half2*)&pk[q]);
                v[fi][q * 2] = f2.x;
                v[fi][q * 2 + 1] = f2.y;
            }
            float s = 0.f;
#pragma unroll
            for (int j = 0; j < 16; ++j) s += hr[j] * v[fi][j];
#pragma unroll
            for (int off = 16; off; off >>= 1) s += __shfl_xor_sync(0xffffffffu, s, off);
            sc[fi] = s;
        }
        float tv = fmaxf(fmaxf(sc[0], sc[1]), fmaxf(sc[2], sc[3]));
        float mn = fmaxf(m, tv);
        float scale = __expf(m - mn);
        m = mn;
        float p0 = __expf(sc[0] - mn), p1 = __expf(sc[1] - mn);
        float p2 = __expf(sc[2] - mn), p3 = __expf(sc[3] - mn);
        sw = sw * scale + (p0 + p1 + p2 + p3);
#pragma unroll
        for (int j = 0; j < 16; ++j)
            acc[j] = acc[j] * scale + p0 * v[0][j] + p1 * v[1][j] + p2 * v[2][j] + p3 * v[3][j];
    }

#pragma unroll
    for (int i = 0; i < 4; ++i) *(float4*)&reds[w][lane * 16 + i * 4] = *(float4*)&acc[i * 4];
    if (lane == 0) { mwarp[w] = m; swarp[w] = sw; }
    __syncthreads();

    float gm = mwarp[0];
#pragma unroll
    for (int ww = 1; ww < 8; ++ww) gm = fmaxf(gm, mwarp[ww]);
    float wsc[8];
    float stot = 0.f;
#pragma unroll
    for (int ww = 0; ww < 8; ++ww) { wsc[ww] = __expf(mwarp[ww] - gm); stot += swarp[ww] * wsc[ww]; }
    float inv = 1.f / stot;
#pragma unroll
    for (int r = 0; r < 2; ++r) {
        int d = tid + r * 256;
        float a = 0.f;
#pragma unroll
        for (int ww = 0; ww < 8; ++ww) a += reds[ww][d] * wsc[ww];
        g_ctx[b * UDIM + d] = a * inv;
    }
}

// ---------------- launcher (graph-capturable: kernel launches only) ----------------
extern "C" void kernel_launch(void* const* d_in, const int* in_sizes, int n_in,
                              void* d_out, int out_size) {
    (void)in_sizes; (void)n_in; (void)out_size;
    const float* h  = (const float*)d_in[0];
    const float* y  = (const float*)d_in[1];
    const float* W1 = (const float*)d_in[2];
    const float* U1 = (const float*)d_in[3];
    const float* b1 = (const float*)d_in[4];
    const float* W2 = (const float*)d_in[5];
    const float* U2 = (const float*)d_in[6];
    const float* b2 = (const float*)d_in[7];
    const float* Wd = (const float*)d_in[8];
    const float* bd = (const float*)d_in[9];
    float* out = (float*)d_out;

    prologue_kernel<<<1024, 256>>>(W1, U1, W2, U2, Wd, h);
    for (int t = 0; t < TT; ++t) {
        ka_kernel<<<192, 256>>>(b2, bd, out, t);
        attn_kernel<<<64, 256>>>(y, b1, t);
        kc_kernel<<<128, 256>>>();
    }
    ep_kernel<<<64, 256>>>(b2, bd, out);
}

// round 7
// speedup vs baseline: 2.3423x; 1.6687x over previous
#include <cuda_runtime.h>
#include <cuda_fp16.h>
#include <cstdint>

#define BB 64
#define TT 256
#define ET 1024
#define UDIM 512
#define VV 46
#define N4 2048
#define KDIM 1024
#define KSPLIT 4

// ---------------- device-global state / scratch (allocation-free) ----------------
__device__ __align__(16) __half g_M1t[(size_t)N4 * KDIM];  // [n][k] fp16: k<512 -> W1[k]+U1[k]; else W1[k+1]
__device__ __align__(16) __half g_M2t[(size_t)N4 * KDIM];  // [n][k] fp16: k<512 -> W2[k]; else U2[k-512]
__device__ __align__(16) float g_r1[N4];                   // W1 row 512 (y_t rank-1 term)
__device__ __align__(16) float g_WdT[VV * KDIM];           // Wd transposed [v][k]
__device__ __align__(16) __half g_hh[(size_t)BB * ET * UDIM];  // fp16 encoder h
__device__ __align__(16) __half g_h1h[BB * UDIM];
__device__ __align__(16) __half g_ctxh[BB * UDIM];
__device__ __align__(16) __half g_h2h[BB * UDIM];
__device__ __align__(16) float g_c1[BB * UDIM];
__device__ __align__(16) float g_c2[BB * UDIM];
__device__ __align__(16) float g_ctx[BB * UDIM];
__device__ __align__(16) float g_z1p[KSPLIT * BB * N4];
__device__ __align__(16) float g_z2p[KSPLIT * BB * N4];

__device__ __forceinline__ float sigf(float x) { return 1.f / (1.f + __expf(-x)); }

__device__ __forceinline__ void cpa16(void* smem, const void* g) {
    unsigned s = (unsigned)__cvta_generic_to_shared(smem);
    asm volatile("cp.async.cg.shared.global [%0], [%1], 16;" :: "r"(s), "l"(g));
}
__device__ __forceinline__ void cpcommit() { asm volatile("cp.async.commit_group;"); }
template <int N> __device__ __forceinline__ void cpwait() {
    asm volatile("cp.async.wait_group %0;" :: "n"(N));
}

// ---------------- prologue ----------------
__global__ void prologue_kernel(const float* __restrict__ W1, const float* __restrict__ U1,
                                const float* __restrict__ W2, const float* __restrict__ U2,
                                const float* __restrict__ Wd, const float* __restrict__ h) {
    int stride = gridDim.x * blockDim.x;
    int t0 = blockIdx.x * blockDim.x + threadIdx.x;
    for (size_t idx = t0; idx < (size_t)N4 * KDIM; idx += stride) {
        int n = idx >> 10;
        int k = idx & (KDIM - 1);
        float m1 = (k < UDIM) ? (W1[(size_t)k * N4 + n] + U1[(size_t)k * N4 + n])
                              : W1[(size_t)(k + 1) * N4 + n];
        float m2 = (k < UDIM) ? W2[(size_t)k * N4 + n] : U2[(size_t)(k - UDIM) * N4 + n];
        g_M1t[idx] = __float2half_rn(m1);
        g_M2t[idx] = __float2half_rn(m2);
    }
    for (int j = t0; j < N4; j += stride) g_r1[j] = W1[UDIM * N4 + j];
    for (int idx = t0; idx < VV * KDIM; idx += stride) {
        int v = idx / KDIM, k = idx % KDIM;
        g_WdT[idx] = Wd[k * VV + v];
    }
    for (size_t idx = t0; idx < (size_t)BB * ET * UDIM; idx += stride)
        g_hh[idx] = __float2half_rn(h[idx]);
    for (int i = t0; i < BB * UDIM; i += stride) {
        g_c1[i] = 0.f; g_c2[i] = 0.f; g_ctx[i] = 0.f;
        g_h1h[i] = __float2half_rn(0.f);
        g_ctxh[i] = __float2half_rn(0.f);
        g_h2h[i] = __float2half_rn(0.f);
    }
}

// ---------------- fp16 tensor-core split-K GEMM ----------------
// C[64 x 2048] += A[64 x 1024]fp16 @ B[1024 x 2048]fp16, B stored [n][k].
// Block: jt = id&31 (N-tile of 64), kc = id>>5 (K-chunk of 256, two 128-k phases).
// A(b,k) = k<512 ? A0 : A1 (chunks don't straddle).
#define PADK 136
__device__ __forceinline__ void gemm_body(int id, const __half* __restrict__ A0,
                                          const __half* __restrict__ A1,
                                          const __half* __restrict__ Bw,
                                          float* __restrict__ zp) {
    int jt = id & 31;
    int kc = id >> 5;
    int jbase = jt * 64;
    const __half* Asrc = (kc < 2) ? A0 : A1;
    int koff0 = (kc & 1) * 256;

    __shared__ __align__(16) __half As[64 * PADK];
    __shared__ __align__(16) __half Bs[64 * PADK];

    int tid = threadIdx.x;
    int w = tid >> 5, lane = tid & 31;
    int wr = w >> 2, wc = w & 3;           // warp grid 2 x 4
    int m_base = wr * 32, n_base = wc * 16;
    int g = lane >> 2, tg = lane & 3;

    float c[2][2][4];
#pragma unroll
    for (int mt = 0; mt < 2; ++mt)
#pragma unroll
        for (int nt = 0; nt < 2; ++nt)
#pragma unroll
            for (int q = 0; q < 4; ++q) c[mt][nt][q] = 0.f;

    for (int p = 0; p < 2; ++p) {
        int k0 = kc * 256 + p * 128;       // global k for B
        int koff = koff0 + p * 128;        // k offset within A source
        // load As / Bs: 64 rows x 128 halfs each = 1024 chunks of 8 halfs (16 chunks/row)
#pragma unroll
        for (int q = 0; q < 4; ++q) {
            int chunk = tid + q * 256;     // 0..1023
            int r = chunk >> 4;            // 0..63
            int c8 = (chunk & 15) * 8;     // 0..120
            cpa16(&As[r * PADK + c8], Asrc + (size_t)r * UDIM + koff + c8);
            cpa16(&Bs[r * PADK + c8], Bw + (size_t)(jbase + r) * KDIM + k0 + c8);
        }
        cpcommit();
        cpwait<0>();
        __syncthreads();

#pragma unroll
        for (int ks = 0; ks < 8; ++ks) {
            unsigned a[2][4], bfr[2][2];
#pragma unroll
            for (int mt = 0; mt < 2; ++mt) {
                int row = m_base + mt * 16 + g;
                const __half* base0 = &As[row * PADK + ks * 16 + tg * 2];
                a[mt][0] = *(const unsigned*)base0;
                a[mt][1] = *(const unsigned*)(base0 + 8 * PADK);
                a[mt][2] = *(const unsigned*)(base0 + 8);
                a[mt][3] = *(const unsigned*)(base0 + 8 * PADK + 8);
            }
#pragma unroll
            for (int nt = 0; nt < 2; ++nt) {
                int col = n_base + nt * 8 + g;
                const __half* base0 = &Bs[col * PADK + ks * 16 + tg * 2];
                bfr[nt][0] = *(const unsigned*)base0;
                bfr[nt][1] = *(const unsigned*)(base0 + 8);
            }
#pragma unroll
            for (int mt = 0; mt < 2; ++mt)
#pragma unroll
                for (int nt = 0; nt < 2; ++nt) {
                    asm volatile(
                        "mma.sync.aligned.m16n8k16.row.col.f32.f16.f16.f32 "
                        "{%0,%1,%2,%3}, {%4,%5,%6,%7}, {%8,%9}, {%0,%1,%2,%3};"
                        : "+f"(c[mt][nt][0]), "+f"(c[mt][nt][1]),
                          "+f"(c[mt][nt][2]), "+f"(c[mt][nt][3])
                        : "r"(a[mt][0]), "r"(a[mt][1]), "r"(a[mt][2]), "r"(a[mt][3]),
                          "r"(bfr[nt][0]), "r"(bfr[nt][1]));
                }
        }
        __syncthreads();
    }

    float* zb = zp + (size_t)kc * BB * N4;
#pragma unroll
    for (int mt = 0; mt < 2; ++mt)
#pragma unroll
        for (int nt = 0; nt < 2; ++nt) {
            int row0 = m_base + mt * 16 + g;
            int col0 = jbase + n_base + nt * 8 + tg * 2;
            float2 lo = make_float2(c[mt][nt][0], c[mt][nt][1]);
            float2 hi = make_float2(c[mt][nt][2], c[mt][nt][3]);
            *(float2*)(zb + (size_t)row0 * N4 + col0) = lo;
            *(float2*)(zb + (size_t)(row0 + 8) * N4 + col0) = hi;
        }
}

// ---------------- LSTM2 gate finish + logits + output softmax for step tprev ----------------
__device__ __forceinline__ void dec_body(int b, int tprev, const float* __restrict__ b2,
                                         const float* __restrict__ bd, float* __restrict__ out) {
    __shared__ __align__(16) float xcat[2 * UDIM];
    __shared__ float lg[VV];
    int tid = threadIdx.x;
#pragma unroll
    for (int r = 0; r < 2; ++r) {
        int u = tid + r * 256;
        float z[4];
#pragma unroll
        for (int g = 0; g < 4; ++g) {
            int idx = g * UDIM + u;
            float v = b2[idx];
#pragma unroll
            for (int kc = 0; kc < KSPLIT; ++kc) v += g_z2p[(size_t)(kc * BB + b) * N4 + idx];
            z[g] = v;
        }
        float co = g_c2[b * UDIM + u];
        float cn = sigf(z[1]) * co + sigf(z[0]) * tanhf(z[2]);
        float hn = sigf(z[3]) * tanhf(cn);
        g_c2[b * UDIM + u] = cn;
        g_h2h[b * UDIM + u] = __float2half_rn(hn);
        xcat[u] = hn;
        xcat[UDIM + u] = g_ctx[b * UDIM + u];
    }
    __syncthreads();
    int lane = tid & 31, w = tid >> 5;
    for (int v = w; v < VV; v += 8) {
        float p = 0.f;
        const float* wr = g_WdT + v * KDIM;
        for (int k = lane; k < KDIM; k += 32) p += xcat[k] * wr[k];
#pragma unroll
        for (int off = 16; off; off >>= 1) p += __shfl_xor_sync(0xffffffffu, p, off);
        if (lane == 0) lg[v] = p + bd[v];
    }
    __syncthreads();
    if (tid == 0) {
        float mx = lg[0];
        for (int v = 1; v < VV; ++v) mx = fmaxf(mx, lg[v]);
        float s = 0.f;
        for (int v = 0; v < VV; ++v) { float e = __expf(lg[v] - mx); lg[v] = e; s += e; }
        float inv = 1.f / s;
        for (int v = 0; v < VV; ++v) lg[v] *= inv;
    }
    __syncthreads();
    if (tid < VV) out[((size_t)b * TT + tprev) * VV + tid] = lg[tid];
}

// ---------------- KA: z1 GEMM (blocks 0..127) + prev-step LSTM2/logits (128..191) ----------------
__global__ void __launch_bounds__(256) ka_kernel(const float* __restrict__ b2,
                                                 const float* __restrict__ bd,
                                                 float* __restrict__ out, int t) {
    if (blockIdx.x < 128) {
        gemm_body(blockIdx.x, g_h1h, g_ctxh, g_M1t, g_z1p);
    } else if (t > 0) {
        dec_body(blockIdx.x - 128, t - 1, b2, bd, out);
    }
}

__global__ void __launch_bounds__(256) kc_kernel() {
    gemm_body(blockIdx.x, g_ctxh, g_h2h, g_M2t, g_z2p);
}

__global__ void __launch_bounds__(256) ep_kernel(const float* __restrict__ b2,
                                                 const float* __restrict__ bd,
                                                 float* __restrict__ out) {
    dec_body(blockIdx.x, TT - 1, b2, bd, out);
}

// ---------------- KB: LSTM1 gate finish + per-warp online-softmax attention over fp16 h ----------------
__global__ void __launch_bounds__(256) attn_kernel(const float* __restrict__ yv,
                                                   const float* __restrict__ b1, int t) {
    int b = blockIdx.x;
    int tid = threadIdx.x;
    int lane = tid & 31, w = tid >> 5;
    __shared__ __align__(16) float h1s[UDIM];
    __shared__ __align__(16) float reds[8][UDIM];
    __shared__ float mwarp[8], swarp[8];

    float yb = yv[b * TT + t];
#pragma unroll
    for (int r = 0; r < 2; ++r) {
        int u = tid + r * 256;
        float z[4];
#pragma unroll
        for (int g = 0; g < 4; ++g) {
            int idx = g * UDIM + u;
            float vvv = b1[idx] + yb * g_r1[idx];
#pragma unroll
            for (int kc = 0; kc < KSPLIT; ++kc) vvv += g_z1p[(size_t)(kc * BB + b) * N4 + idx];
            z[g] = vvv;
        }
        float co = g_c1[b * UDIM + u];
        float cn = sigf(z[1]) * co + sigf(z[0]) * tanhf(z[2]);
        float hn = sigf(z[3]) * tanhf(cn);
        g_c1[b * UDIM + u] = cn;
        g_h1h[b * UDIM + u] = __float2half_rn(hn);
        h1s[u] = hn;
    }
    __syncthreads();

    float hr[16];
#pragma unroll
    for (int i = 0; i < 4; ++i) *(float4*)&hr[i * 4] = *(const float4*)&h1s[lane * 16 + i * 4];

    float acc[16];
#pragma unroll
    for (int j = 0; j < 16; ++j) acc[j] = 0.f;
    float m = -1e30f, sw = 0.f;
    const __half* hb = g_hh + (size_t)b * ET * UDIM;

    for (int tile = 0; tile < ET / 32; ++tile) {
        int f0 = tile * 32 + w * 4;
        float v[4][16];
        float sc[4];
#pragma unroll
        for (int fi = 0; fi < 4; ++fi) {
            const __half* hf = hb + (size_t)(f0 + fi) * UDIM + lane * 16;
            uint4 p0 = *(const uint4*)hf;
            uint4 p1 = *(const uint4*)(hf + 8);
            const unsigned pk[8] = {p0.x, p0.y, p0.z, p0.w, p1.x, p1.y, p1.z, p1.w};
#pragma unroll
            for (int q = 0; q < 8; ++q) {
                float2 f2 = __half22float2(*(const __half2*)&pk[q]);
                v[fi][q * 2] = f2.x;
                v[fi][q * 2 + 1] = f2.y;
            }
            float s = 0.f;
#pragma unroll
            for (int j = 0; j < 16; ++j) s += hr[j] * v[fi][j];
#pragma unroll
            for (int off = 16; off; off >>= 1) s += __shfl_xor_sync(0xffffffffu, s, off);
            sc[fi] = s;
        }
        float tv = fmaxf(fmaxf(sc[0], sc[1]), fmaxf(sc[2], sc[3]));
        float mn = fmaxf(m, tv);
        float scale = __expf(m - mn);
        m = mn;
        float p0 = __expf(sc[0] - mn), p1 = __expf(sc[1] - mn);
        float p2 = __expf(sc[2] - mn), p3 = __expf(sc[3] - mn);
        sw = sw * scale + (p0 + p1 + p2 + p3);
#pragma unroll
        for (int j = 0; j < 16; ++j)
            acc[j] = acc[j] * scale + p0 * v[0][j] + p1 * v[1][j] + p2 * v[2][j] + p3 * v[3][j];
    }

#pragma unroll
    for (int i = 0; i < 4; ++i) *(float4*)&reds[w][lane * 16 + i * 4] = *(float4*)&acc[i * 4];
    if (lane == 0) { mwarp[w] = m; swarp[w] = sw; }
    __syncthreads();

    float gm = mwarp[0];
#pragma unroll
    for (int ww = 1; ww < 8; ++ww) gm = fmaxf(gm, mwarp[ww]);
    float wsc[8];
    float stot = 0.f;
#pragma unroll
    for (int ww = 0; ww < 8; ++ww) { wsc[ww] = __expf(mwarp[ww] - gm); stot += swarp[ww] * wsc[ww]; }
    float inv = 1.f / stot;
#pragma unroll
    for (int r = 0; r < 2; ++r) {
        int d = tid + r * 256;
        float a = 0.f;
#pragma unroll
        for (int ww = 0; ww < 8; ++ww) a += reds[ww][d] * wsc[ww];
        float cv = a * inv;
        g_ctx[b * UDIM + d] = cv;
        g_ctxh[b * UDIM + d] = __float2half_rn(cv);
    }
}

// ---------------- launcher (graph-capturable: kernel launches only) ----------------
extern "C" void kernel_launch(void* const* d_in, const int* in_sizes, int n_in,
                              void* d_out, int out_size) {
    (void)in_sizes; (void)n_in; (void)out_size;
    const float* h  = (const float*)d_in[0];
    const float* y  = (const float*)d_in[1];
    const float* W1 = (const float*)d_in[2];
    const float* U1 = (const float*)d_in[3];
    const float* b1 = (const float*)d_in[4];
    const float* W2 = (const float*)d_in[5];
    const float* U2 = (const float*)d_in[6];
    const float* b2 = (const float*)d_in[7];
    const float* Wd = (const float*)d_in[8];
    const float* bd = (const float*)d_in[9];
    float* out = (float*)d_out;

    prologue_kernel<<<1024, 256>>>(W1, U1, W2, U2, Wd, h);
    for (int t = 0; t < TT; ++t) {
        ka_kernel<<<192, 256>>>(b2, bd, out, t);
        attn_kernel<<<64, 256>>>(y, b1, t);
        kc_kernel<<<128, 256>>>();
    }
    ep_kernel<<<64, 256>>>(b2, bd, out);
}

// round 10
// speedup vs baseline: 3.0745x; 1.3126x over previous
#include <cuda_runtime.h>
#include <cuda_fp16.h>
#include <cstdint>

#define BB 64
#define TT 256
#define ET 1024
#define UDIM 512
#define VV 46
#define N4 2048
#define KDIM 1024
#define KSPLIT 4
#define PADK2 72

// ---------------- device-global state / scratch (allocation-free) ----------------
__device__ __align__(16) __half g_M1t[(size_t)N4 * KDIM];  // [n][k] fp16: k<512 -> W1[k]+U1[k]; else W1[k+1]
__device__ __align__(16) __half g_M2t[(size_t)N4 * KDIM];  // [n][k] fp16: k<512 -> W2[k]; else U2[k-512]
__device__ __align__(16) float g_r1[N4];                   // W1 row 512 (y_t rank-1 term)
__device__ __align__(16) float g_WdT[VV * KDIM];           // Wd transposed [v][k]
__device__ __align__(16) __half g_hh[(size_t)BB * ET * UDIM];  // fp16 encoder h
__device__ __align__(16) __half g_h1h[BB * UDIM];
__device__ __align__(16) __half g_ctxh[BB * UDIM];
__device__ __align__(16) __half g_h2h[BB * UDIM];
__device__ __align__(16) float g_c1[2 * BB * UDIM];        // double-buffered by t parity
__device__ __align__(16) float g_c2[BB * UDIM];
__device__ __align__(16) float g_ctx[BB * UDIM];
__device__ __align__(16) float g_z1p[KSPLIT * BB * N4];
__device__ __align__(16) float g_z2p[KSPLIT * BB * N4];
// attention partials (4 frame-slices per row) + completion counters
__device__ __align__(16) float g_accp[BB * 4 * UDIM];
__device__ float g_mp[BB * 4];
__device__ float g_sp[BB * 4];
__device__ int g_cnt[BB];

__device__ __forceinline__ float sigf(float x) { return 1.f / (1.f + __expf(-x)); }

__device__ __forceinline__ void cpa16(void* smem, const void* g) {
    unsigned s = (unsigned)__cvta_generic_to_shared(smem);
    asm volatile("cp.async.cg.shared.global [%0], [%1], 16;" :: "r"(s), "l"(g));
}
__device__ __forceinline__ void cpcommit() { asm volatile("cp.async.commit_group;"); }
template <int N> __device__ __forceinline__ void cpwait() {
    asm volatile("cp.async.wait_group %0;" :: "n"(N));
}

// ---------------- prologue ----------------
__global__ void prologue_kernel(const float* __restrict__ W1, const float* __restrict__ U1,
                                const float* __restrict__ W2, const float* __restrict__ U2,
                                const float* __restrict__ Wd, const float* __restrict__ h) {
    int stride = gridDim.x * blockDim.x;
    int t0 = blockIdx.x * blockDim.x + threadIdx.x;
    for (size_t idx = t0; idx < (size_t)N4 * KDIM; idx += stride) {
        int n = idx >> 10;
        int k = idx & (KDIM - 1);
        float m1 = (k < UDIM) ? (W1[(size_t)k * N4 + n] + U1[(size_t)k * N4 + n])
                              : W1[(size_t)(k + 1) * N4 + n];
        float m2 = (k < UDIM) ? W2[(size_t)k * N4 + n] : U2[(size_t)(k - UDIM) * N4 + n];
        g_M1t[idx] = __float2half_rn(m1);
        g_M2t[idx] = __float2half_rn(m2);
    }
    for (int j = t0; j < N4; j += stride) g_r1[j] = W1[UDIM * N4 + j];
    for (int idx = t0; idx < VV * KDIM; idx += stride) {
        int v = idx / KDIM, k = idx % KDIM;
        g_WdT[idx] = Wd[k * VV + v];
    }
    for (size_t idx = t0; idx < (size_t)BB * ET * UDIM; idx += stride)
        g_hh[idx] = __float2half_rn(h[idx]);
    for (int i = t0; i < BB * UDIM; i += stride) {
        g_c1[i] = 0.f; g_c1[BB * UDIM + i] = 0.f;
        g_c2[i] = 0.f; g_ctx[i] = 0.f;
        g_h1h[i] = __float2half_rn(0.f);
        g_ctxh[i] = __float2half_rn(0.f);
        g_h2h[i] = __float2half_rn(0.f);
    }
    for (int i = t0; i < BB; i += stride) g_cnt[i] = 0;
}

// ---------------- fp16 tensor-core split-K GEMM, depth-2 cp.async pipeline ----------------
// C[64 x 2048] += A[64 x 1024]fp16 @ B[1024 x 2048]fp16, B stored [n][k].
// Block: jt = id&31 (N-tile of 64), kc = id>>5 (K-chunk of 256 = 4 stages of 64).
__device__ __forceinline__ void gemm_issue(int buf, int stage, const __half* __restrict__ Asrc,
                                           int koff0, const __half* __restrict__ Bw,
                                           int jbase, int kcbase, __half* As, __half* Bs, int tid) {
    int kA = koff0 + stage * 64;
    int kB = kcbase + stage * 64;
    __half* Ab = As + buf * (64 * PADK2);
    __half* Bb = Bs + buf * (64 * PADK2);
#pragma unroll
    for (int q = 0; q < 2; ++q) {
        int chunk = tid + q * 256;         // 0..511
        int r = chunk >> 3;                // 0..63
        int c8 = (chunk & 7) * 8;          // 0..56
        cpa16(&Ab[r * PADK2 + c8], Asrc + (size_t)r * UDIM + kA + c8);
        cpa16(&Bb[r * PADK2 + c8], Bw + (size_t)(jbase + r) * KDIM + kB + c8);
    }
    cpcommit();
}

__device__ __forceinline__ void gemm_body(int id, const __half* __restrict__ A0,
                                          const __half* __restrict__ A1,
                                          const __half* __restrict__ Bw,
                                          float* __restrict__ zp) {
    int jt = id & 31;
    int kc = id >> 5;
    int jbase = jt * 64;
    int kcbase = kc * 256;
    const __half* Asrc = (kc < 2) ? A0 : A1;
    int koff0 = (kc & 1) * 256;

    __shared__ __align__(16) __half As[2 * 64 * PADK2];
    __shared__ __align__(16) __half Bs[2 * 64 * PADK2];

    int tid = threadIdx.x;
    int w = tid >> 5, lane = tid & 31;
    int wr = w >> 2, wc = w & 3;           // warp grid 2 x 4
    int m_base = wr * 32, n_base = wc * 16;
    int g = lane >> 2, tg = lane & 3;

    float c[2][2][4];
#pragma unroll
    for (int mt = 0; mt < 2; ++mt)
#pragma unroll
        for (int nt = 0; nt < 2; ++nt)
#pragma unroll
            for (int q = 0; q < 4; ++q) c[mt][nt][q] = 0.f;

    gemm_issue(0, 0, Asrc, koff0, Bw, jbase, kcbase, As, Bs, tid);
    gemm_issue(1, 1, Asrc, koff0, Bw, jbase, kcbase, As, Bs, tid);

    for (int s = 0; s < 4; ++s) {
        if (s < 3) cpwait<1>(); else cpwait<0>();
        __syncthreads();
        int bf = s & 1;
        const __half* Ab = As + bf * (64 * PADK2);
        const __half* Bb = Bs + bf * (64 * PADK2);
#pragma unroll
        for (int ks = 0; ks < 4; ++ks) {
            unsigned a[2][4], bfr[2][2];
#pragma unroll
            for (int mt = 0; mt < 2; ++mt) {
                int row = m_base + mt * 16 + g;
                const __half* base0 = &Ab[row * PADK2 + ks * 16 + tg * 2];
                a[mt][0] = *(const unsigned*)base0;
                a[mt][1] = *(const unsigned*)(base0 + 8 * PADK2);
                a[mt][2] = *(const unsigned*)(base0 + 8);
                a[mt][3] = *(const unsigned*)(base0 + 8 * PADK2 + 8);
            }
#pragma unroll
            for (int nt = 0; nt < 2; ++nt) {
                int col = n_base + nt * 8 + g;
                const __half* base0 = &Bb[col * PADK2 + ks * 16 + tg * 2];
                bfr[nt][0] = *(const unsigned*)base0;
                bfr[nt][1] = *(const unsigned*)(base0 + 8);
            }
#pragma unroll
            for (int mt = 0; mt < 2; ++mt)
#pragma unroll
                for (int nt = 0; nt < 2; ++nt) {
                    asm volatile(
                        "mma.sync.aligned.m16n8k16.row.col.f32.f16.f16.f32 "
                        "{%0,%1,%2,%3}, {%4,%5,%6,%7}, {%8,%9}, {%0,%1,%2,%3};"
                        : "+f"(c[mt][nt][0]), "+f"(c[mt][nt][1]),
                          "+f"(c[mt][nt][2]), "+f"(c[mt][nt][3])
                        : "r"(a[mt][0]), "r"(a[mt][1]), "r"(a[mt][2]), "r"(a[mt][3]),
                          "r"(bfr[nt][0]), "r"(bfr[nt][1]));
                }
        }
        if (s + 2 < 4) {
            __syncthreads();               // all warps done reading buf before refill
            gemm_issue(bf, s + 2, Asrc, koff0, Bw, jbase, kcbase, As, Bs, tid);
        }
    }

    float* zb = zp + (size_t)kc * BB * N4;
#pragma unroll
    for (int mt = 0; mt < 2; ++mt)
#pragma unroll
        for (int nt = 0; nt < 2; ++nt) {
            int row0 = m_base + mt * 16 + g;
            int col0 = jbase + n_base + nt * 8 + tg * 2;
            float2 lo = make_float2(c[mt][nt][0], c[mt][nt][1]);
            float2 hi = make_float2(c[mt][nt][2], c[mt][nt][3]);
            *(float2*)(zb + (size_t)row0 * N4 + col0) = lo;
            *(float2*)(zb + (size_t)(row0 + 8) * N4 + col0) = hi;
        }
}

// ---------------- LSTM2 gate finish + logits + output softmax for step tprev ----------------
__device__ __forceinline__ void dec_body(int b, int tprev, const float* __restrict__ b2,
                                         const float* __restrict__ bd, float* __restrict__ out) {
    __shared__ __align__(16) float xcat[2 * UDIM];
    __shared__ float lg[VV];
    int tid = threadIdx.x;
#pragma unroll
    for (int r = 0; r < 2; ++r) {
        int u = tid + r * 256;
        float z[4];
#pragma unroll
        for (int g = 0; g < 4; ++g) {
            int idx = g * UDIM + u;
            float v = b2[idx];
#pragma unroll
            for (int kc = 0; kc < KSPLIT; ++kc) v += g_z2p[(size_t)(kc * BB + b) * N4 + idx];
            z[g] = v;
        }
        float co = g_c2[b * UDIM + u];
        float cn = sigf(z[1]) * co + sigf(z[0]) * tanhf(z[2]);
        float hn = sigf(z[3]) * tanhf(cn);
        g_c2[b * UDIM + u] = cn;
        g_h2h[b * UDIM + u] = __float2half_rn(hn);
        xcat[u] = hn;
        xcat[UDIM + u] = g_ctx[b * UDIM + u];
    }
    __syncthreads();
    int lane = tid & 31, w = tid >> 5;
    for (int v = w; v < VV; v += 8) {
        float p = 0.f;
        const float* wr = g_WdT + v * KDIM;
        for (int k = lane; k < KDIM; k += 32) p += xcat[k] * wr[k];
#pragma unroll
        for (int off = 16; off; off >>= 1) p += __shfl_xor_sync(0xffffffffu, p, off);
        if (lane == 0) lg[v] = p + bd[v];
    }
    __syncthreads();
    if (tid == 0) {
        float mx = lg[0];
        for (int v = 1; v < VV; ++v) mx = fmaxf(mx, lg[v]);
        float s = 0.f;
        for (int v = 0; v < VV; ++v) { float e = __expf(lg[v] - mx); lg[v] = e; s += e; }
        float inv = 1.f / s;
        for (int v = 0; v < VV; ++v) lg[v] *= inv;
    }
    __syncthreads();
    if (tid < VV) out[((size_t)b * TT + tprev) * VV + tid] = lg[tid];
}

// ---------------- KA: z1 GEMM (blocks 0..127) + prev-step LSTM2/logits (128..191) ----------------
__global__ void __launch_bounds__(256) ka_kernel(const float* __restrict__ b2,
                                                 const float* __restrict__ bd,
                                                 float* __restrict__ out, int t) {
    if (blockIdx.x < 128) {
        gemm_body(blockIdx.x, g_h1h, g_ctxh, g_M1t, g_z1p);
    } else if (t > 0) {
        dec_body(blockIdx.x - 128, t - 1, b2, bd, out);
    }
}

__global__ void __launch_bounds__(256) kc_kernel() {
    gemm_body(blockIdx.x, g_ctxh, g_h2h, g_M2t, g_z2p);
}

__global__ void __launch_bounds__(256) ep_kernel(const float* __restrict__ b2,
                                                 const float* __restrict__ bd,
                                                 float* __restrict__ out) {
    dec_body(blockIdx.x, TT - 1, b2, bd, out);
}

// ---------------- KB: LSTM1 gates + 4-way-split online-softmax attention + in-kernel combine ----
// grid = 256: p = blockIdx.x & 3 (frame slice of 256), b = blockIdx.x >> 2 (batch row).
__global__ void __launch_bounds__(256) attn_kernel(const float* __restrict__ yv,
                                                   const float* __restrict__ b1, int t) {
    int p = blockIdx.x & 3;
    int b = blockIdx.x >> 2;
    int tid = threadIdx.x;
    int lane = tid & 31, w = tid >> 5;
    __shared__ __align__(16) float h1s[UDIM];
    __shared__ __align__(16) float reds[8][UDIM];
    __shared__ float mwarp[8], swarp[8];
    __shared__ int is_last;

    int par = t & 1;
    const float* c1r = g_c1 + par * BB * UDIM;
    float* c1w = g_c1 + (1 - par) * BB * UDIM;

    float yb = yv[b * TT + t];
#pragma unroll
    for (int r = 0; r < 2; ++r) {
        int u = tid + r * 256;
        float z[4];
#pragma unroll
        for (int g = 0; g < 4; ++g) {
            int idx = g * UDIM + u;
            float vvv = b1[idx] + yb * g_r1[idx];
#pragma unroll
            for (int kc = 0; kc < KSPLIT; ++kc) vvv += g_z1p[(size_t)(kc * BB + b) * N4 + idx];
            z[g] = vvv;
        }
        float co = c1r[b * UDIM + u];
        float cn = sigf(z[1]) * co + sigf(z[0]) * tanhf(z[2]);
        float hn = sigf(z[3]) * tanhf(cn);
        if (p == 0) {
            c1w[b * UDIM + u] = cn;
            g_h1h[b * UDIM + u] = __float2half_rn(hn);
        }
        h1s[u] = hn;
    }
    __syncthreads();

    float hr[16];
#pragma unroll
    for (int i = 0; i < 4; ++i) *(float4*)&hr[i * 4] = *(const float4*)&h1s[lane * 16 + i * 4];

    float acc[16];
#pragma unroll
    for (int j = 0; j < 16; ++j) acc[j] = 0.f;
    float m = -1e30f, sw = 0.f;
    const __half* hb = g_hh + (size_t)b * ET * UDIM;

    for (int tile = 0; tile < 8; ++tile) {
        int f0 = p * 256 + tile * 32 + w * 4;
        float v[4][16];
        float sc[4];
#pragma unroll
        for (int fi = 0; fi < 4; ++fi) {
            const __half* hf = hb + (size_t)(f0 + fi) * UDIM + lane * 16;
            uint4 p0 = *(const uint4*)hf;
            uint4 p1 = *(const uint4*)(hf + 8);
            const unsigned pk[8] = {p0.x, p0.y, p0.z, p0.w, p1.x, p1.y, p1.z, p1.w};
#pragma unroll
            for (int q = 0; q < 8; ++q) {
                float2 f2 = __half22float2(*(const __half2*)&pk[q]);
                v[fi][q * 2] = f2.x;
                v[fi][q * 2 + 1] = f2.y;
            }
            float s = 0.f;
#pragma unroll
            for (int j = 0; j < 16; ++j) s += hr[j] * v[fi][j];
#pragma unroll
            for (int off = 16; off; off >>= 1) s += __shfl_xor_sync(0xffffffffu, s, off);
            sc[fi] = s;
        }
        float tv = fmaxf(fmaxf(sc[0], sc[1]), fmaxf(sc[2], sc[3]));
        float mn = fmaxf(m, tv);
        float scale = __expf(m - mn);
        m = mn;
        float p0 = __expf(sc[0] - mn), p1 = __expf(sc[1] - mn);
        float p2 = __expf(sc[2] - mn), p3 = __expf(sc[3] - mn);
        sw = sw * scale + (p0 + p1 + p2 + p3);
#pragma unroll
        for (int j = 0; j < 16; ++j)
            acc[j] = acc[j] * scale + p0 * v[0][j] + p1 * v[1][j] + p2 * v[2][j] + p3 * v[3][j];
    }

#pragma unroll
    for (int i = 0; i < 4; ++i) *(float4*)&reds[w][lane * 16 + i * 4] = *(float4*)&acc[i * 4];
    if (lane == 0) { mwarp[w] = m; swarp[w] = sw; }
    __syncthreads();

    // block-level partial: combine this block's 8 warps
    float gm = mwarp[0];
#pragma unroll
    for (int ww = 1; ww < 8; ++ww) gm = fmaxf(gm, mwarp[ww]);
    float wsc[8];
    float sb = 0.f;
#pragma unroll
    for (int ww = 0; ww < 8; ++ww) { wsc[ww] = __expf(mwarp[ww] - gm); sb += swarp[ww] * wsc[ww]; }
    float* accp = g_accp + (size_t)(b * 4 + p) * UDIM;
#pragma unroll
    for (int r = 0; r < 2; ++r) {
        int d = tid + r * 256;
        float a = 0.f;
#pragma unroll
        for (int ww = 0; ww < 8; ++ww) a += reds[ww][d] * wsc[ww];
        accp[d] = a;
    }
    if (tid == 0) { g_mp[b * 4 + p] = gm; g_sp[b * 4 + p] = sb; }
    __threadfence();
    __syncthreads();
    if (tid == 0) {
        int old = atomicAdd(&g_cnt[b], 1);
        is_last = (old == 3);
    }
    __syncthreads();
    if (!is_last) return;
    __threadfence();
    if (tid == 0) g_cnt[b] = 0;

    // final combine of the 4 slice partials
    float mp4[4], sp4[4];
#pragma unroll
    for (int q = 0; q < 4; ++q) { mp4[q] = g_mp[b * 4 + q]; sp4[q] = g_sp[b * 4 + q]; }
    float gm4 = fmaxf(fmaxf(mp4[0], mp4[1]), fmaxf(mp4[2], mp4[3]));
    float wsc4[4];
    float stot = 0.f;
#pragma unroll
    for (int q = 0; q < 4; ++q) { wsc4[q] = __expf(mp4[q] - gm4); stot += sp4[q] * wsc4[q]; }
    float inv = 1.f / stot;
#pragma unroll
    for (int r = 0; r < 2; ++r) {
        int d = tid + r * 256;
        float a = 0.f;
#pragma unroll
        for (int q = 0; q < 4; ++q) a += g_accp[(size_t)(b * 4 + q) * UDIM + d] * wsc4[q];
        float cv = a * inv;
        g_ctx[b * UDIM + d] = cv;
        g_ctxh[b * UDIM + d] = __float2half_rn(cv);
    }
}

// ---------------- launcher (graph-capturable: kernel launches only) ----------------
extern "C" void kernel_launch(void* const* d_in, const int* in_sizes, int n_in,
                              void* d_out, int out_size) {
    (void)in_sizes; (void)n_in; (void)out_size;
    const float* h  = (const float*)d_in[0];
    const float* y  = (const float*)d_in[1];
    const float* W1 = (const float*)d_in[2];
    const float* U1 = (const float*)d_in[3];
    const float* b1 = (const float*)d_in[4];
    const float* W2 = (const float*)d_in[5];
    const float* U2 = (const float*)d_in[6];
    const float* b2 = (const float*)d_in[7];
    const float* Wd = (const float*)d_in[8];
    const float* bd = (const float*)d_in[9];
    float* out = (float*)d_out;

    prologue_kernel<<<1024, 256>>>(W1, U1, W2, U2, Wd, h);
    for (int t = 0; t < TT; ++t) {
        ka_kernel<<<192, 256>>>(b2, bd, out, t);
        attn_kernel<<<256, 256>>>(y, b1, t);
        kc_kernel<<<128, 256>>>();
    }
    ep_kernel<<<64, 256>>>(b2, bd, out);
}